// round 17
// baseline (speedup 1.0000x reference)
#include <cuda_runtime.h>
#include <math.h>
#include <stdint.h>

#define NVERT 2562
#define DEPTH 8
#define NTOK  (NVERT * DEPTH)   // 20496
#define CDIM  512
#define NHEAD 8
#define HD    64
#define KNBR  8
#define HID   2048
#define C3    1536
#define LN_EPS 1e-5f
#define KT    16                // GEMM k-tile
#define SMP   136               // smem row stride (floats): conflict-free frags

// ---------------- scratch (device globals; no allocation allowed) -------------
__device__ float g_xn [(size_t)NTOK * CDIM];
__device__ float g_qkv[(size_t)NTOK * C3];
__device__ float g_y  [(size_t)NTOK * CDIM];
__device__ float g_x1 [(size_t)NTOK * CDIM];
__device__ float g_h  [(size_t)NTOK * HID];

// ---------------- helpers ------------------------------------------------------
// split v into tf32 hi + tf32 lo (3xTF32 error compensation)
__device__ __forceinline__ void split_tf32(float v, uint32_t& hi, uint32_t& lo) {
    asm("cvt.rna.tf32.f32 %0, %1;" : "=r"(hi) : "f"(v));
    const float r = v - __uint_as_float(hi);
    asm("cvt.rna.tf32.f32 %0, %1;" : "=r"(lo) : "f"(r));
}

// m16n8k8 tf32 MMA (sm_80+ portable; compiles for plain sm_103)
__device__ __forceinline__ void mma16n8k8(float* c, const uint32_t* a,
                                          const uint32_t* b) {
    asm volatile(
        "mma.sync.aligned.m16n8k8.row.col.f32.tf32.tf32.f32 "
        "{%0,%1,%2,%3}, {%4,%5,%6,%7}, {%8,%9}, {%0,%1,%2,%3};"
        : "+f"(c[0]), "+f"(c[1]), "+f"(c[2]), "+f"(c[3])
        : "r"(a[0]), "r"(a[1]), "r"(a[2]), "r"(a[3]), "r"(b[0]), "r"(b[1]));
}

// ---------------- LayerNorm: one block (128 thr, float4) per token ------------
__global__ void ln_kernel(const float* __restrict__ x,
                          const float* __restrict__ w,
                          const float* __restrict__ b,
                          float* __restrict__ out)
{
    __shared__ float sred[4];
    __shared__ float sbc;
    const int t   = blockIdx.x;
    const int tid = threadIdx.x;
    const int lane = tid & 31, warp = tid >> 5;
    const float* xr = x + (size_t)t * CDIM;

    float4 v = *(const float4*)(xr + tid * 4);

    float s = (v.x + v.y) + (v.z + v.w);
    #pragma unroll
    for (int o = 16; o > 0; o >>= 1) s += __shfl_xor_sync(0xffffffffu, s, o);
    if (lane == 0) sred[warp] = s;
    __syncthreads();
    if (warp == 0) {
        float r = (lane < 4) ? sred[lane] : 0.f;
        #pragma unroll
        for (int o = 2; o > 0; o >>= 1) r += __shfl_xor_sync(0xffffffffu, r, o);
        if (lane == 0) sbc = r;
    }
    __syncthreads();
    const float m = sbc * (1.0f / CDIM);

    const float d0 = v.x - m, d1 = v.y - m, d2 = v.z - m, d3 = v.w - m;
    float sq = (d0 * d0 + d1 * d1) + (d2 * d2 + d3 * d3);
    #pragma unroll
    for (int o = 16; o > 0; o >>= 1) sq += __shfl_xor_sync(0xffffffffu, sq, o);
    __syncthreads();
    if (lane == 0) sred[warp] = sq;
    __syncthreads();
    if (warp == 0) {
        float r = (lane < 4) ? sred[lane] : 0.f;
        #pragma unroll
        for (int o = 2; o > 0; o >>= 1) r += __shfl_xor_sync(0xffffffffu, r, o);
        if (lane == 0) sbc = r;
    }
    __syncthreads();
    const float inv = rsqrtf(sbc * (1.0f / CDIM) + LN_EPS);

    const int c0 = tid * 4;
    float4 wv = *(const float4*)(w + c0);
    float4 bv = *(const float4*)(b + c0);
    float4 o;
    o.x = d0 * inv * wv.x + bv.x;
    o.y = d1 * inv * wv.y + bv.y;
    o.z = d2 * inv * wv.z + bv.z;
    o.w = d3 * inv * wv.w + bv.w;
    *(float4*)(out + (size_t)t * CDIM + c0) = o;
}

// ---------------- 3xTF32 mma.sync GEMM: C = A[M,K]*B[N,K]^T + bias (+epi) -----
// 128x128 tile, 256 thr = 8 warps (4 M x 2 N), warp tile 32x64 = 2x8 m16n8k8.
// fp32 in smem; hi/lo tf32 split at fragment load; 3 MMAs per tile pair:
// Ah*Bh + Al*Bh + Ah*Bl  (error ~2^-21, restores fp32-class accuracy).
// EPI: 0 = bias, 1 = bias + exact GELU, 2 = bias + residual add
template <int EPI, int KDIM>
__global__ void __launch_bounds__(256)
tc_gemm(const float* __restrict__ A, const float* __restrict__ B,
        const float* __restrict__ bias, const float* __restrict__ res,
        float* __restrict__ Cout, int M, int N)
{
    __shared__ float As[2][KT][SMP];
    __shared__ float Bs[2][KT][SMP];

    const int tid  = threadIdx.x;
    const int wid  = tid >> 5;
    const int lane = tid & 31;
    const int qk = lane & 3;        // k offset within quad
    const int qm = lane >> 2;       // row/col-of-8 within fragment
    const int warp_m = (wid & 3) * 32;   // 4 warps down M
    const int warp_n = (wid >> 2) * 64;  // 2 warps across N
    const int row0 = blockIdx.y * 128;
    const int col0 = blockIdx.x * 128;

    // loader mapping (validated on HW in R16): thread -> row lr, k cols lk..lk+7
    const int lr = tid >> 1;
    const int lk = (tid & 1) * 8;
    const int arow = row0 + lr;
    const float* Aptr = A + (size_t)min(arow, M - 1) * KDIM + lk; // clamp tail
    const float* Bptr = B + (size_t)(col0 + lr) * KDIM + lk;      // N mult of 128

    float acc[2][8][4];
    #pragma unroll
    for (int mt = 0; mt < 2; mt++)
        #pragma unroll
        for (int nt = 0; nt < 8; nt++)
            #pragma unroll
            for (int j = 0; j < 4; j++) acc[mt][nt][j] = 0.f;

    // prologue: load k-tile 0, store fp32 to buf 0, sync, prefetch tile 1
    float4 a4[2], b4[2];
    a4[0] = *(const float4*)(Aptr);     a4[1] = *(const float4*)(Aptr + 4);
    b4[0] = *(const float4*)(Bptr);     b4[1] = *(const float4*)(Bptr + 4);
    #pragma unroll
    for (int i = 0; i < 4; i++) {
        As[0][lk + i][lr]     = (&a4[0].x)[i];
        As[0][lk + 4 + i][lr] = (&a4[1].x)[i];
        Bs[0][lk + i][lr]     = (&b4[0].x)[i];
        Bs[0][lk + 4 + i][lr] = (&b4[1].x)[i];
    }
    __syncthreads();
    a4[0] = *(const float4*)(Aptr + KT);  a4[1] = *(const float4*)(Aptr + KT + 4);
    b4[0] = *(const float4*)(Bptr + KT);  b4[1] = *(const float4*)(Bptr + KT + 4);

    int cur = 0;
    #pragma unroll 1
    for (int k0 = 0; k0 < KDIM; k0 += KT) {
        #pragma unroll
        for (int ks = 0; ks < KT; ks += 8) {
            // A fragments: split into hi/lo
            uint32_t ah[2][4], al[2][4];
            #pragma unroll
            for (int mt = 0; mt < 2; mt++) {
                const int m = warp_m + mt * 16 + qm;
                split_tf32(As[cur][ks + qk][m],         ah[mt][0], al[mt][0]);
                split_tf32(As[cur][ks + qk][m + 8],     ah[mt][1], al[mt][1]);
                split_tf32(As[cur][ks + qk + 4][m],     ah[mt][2], al[mt][2]);
                split_tf32(As[cur][ks + qk + 4][m + 8], ah[mt][3], al[mt][3]);
            }
            #pragma unroll
            for (int nt = 0; nt < 8; nt++) {
                const int n = warp_n + nt * 8 + qm;
                uint32_t bh[2], bl[2];
                split_tf32(Bs[cur][ks + qk][n],     bh[0], bl[0]);
                split_tf32(Bs[cur][ks + qk + 4][n], bh[1], bl[1]);
                #pragma unroll
                for (int mt = 0; mt < 2; mt++) {
                    mma16n8k8(acc[mt][nt], ah[mt], bh);   // Ah*Bh
                    mma16n8k8(acc[mt][nt], al[mt], bh);   // Al*Bh
                    mma16n8k8(acc[mt][nt], ah[mt], bl);   // Ah*Bl
                }
            }
        }
        if (k0 + KT < KDIM) {
            const int nxt = cur ^ 1;
            #pragma unroll
            for (int i = 0; i < 4; i++) {
                As[nxt][lk + i][lr]     = (&a4[0].x)[i];
                As[nxt][lk + 4 + i][lr] = (&a4[1].x)[i];
                Bs[nxt][lk + i][lr]     = (&b4[0].x)[i];
                Bs[nxt][lk + 4 + i][lr] = (&b4[1].x)[i];
            }
            __syncthreads();
            if (k0 + 2 * KT < KDIM) {
                const int kn = k0 + 2 * KT;
                a4[0] = *(const float4*)(Aptr + kn);  a4[1] = *(const float4*)(Aptr + kn + 4);
                b4[0] = *(const float4*)(Bptr + kn);  b4[1] = *(const float4*)(Bptr + kn + 4);
            }
            cur = nxt;
        }
    }

    // epilogue: c0,c1 -> (m, n..n+1); c2,c3 -> (m+8, n..n+1)
    #pragma unroll
    for (int mt = 0; mt < 2; mt++) {
        const int mr = row0 + warp_m + mt * 16 + qm;
        #pragma unroll
        for (int nt = 0; nt < 8; nt++) {
            const int nc = col0 + warp_n + nt * 8 + 2 * qk;
            const float bv0 = __ldg(&bias[nc]);
            const float bv1 = __ldg(&bias[nc + 1]);
            #pragma unroll
            for (int half = 0; half < 2; half++) {
                const int r = mr + half * 8;
                if (r >= M) continue;
                float v0 = acc[mt][nt][half * 2 + 0] + bv0;
                float v1 = acc[mt][nt][half * 2 + 1] + bv1;
                if (EPI == 1) {
                    v0 = 0.5f * v0 * (1.0f + erff(v0 * 0.70710678118654752f));
                    v1 = 0.5f * v1 * (1.0f + erff(v1 * 0.70710678118654752f));
                }
                if (EPI == 2) {
                    const float* rr = res + (size_t)r * N + nc;
                    v0 += __ldg(&rr[0]);
                    v1 += __ldg(&rr[1]);
                }
                *(float2*)(Cout + (size_t)r * N + nc) = make_float2(v0, v1);
            }
        }
    }
}

// ---------------- sparse neighbor attention -----------------------------------
__global__ void __launch_bounds__(256)
attn_kernel(const float* __restrict__ qkv,
            const int* __restrict__ which,
            const int* __restrict__ mask,
            float* __restrict__ y)
{
    const int t = blockIdx.x;
    const int n = t / DEPTH;
    const int d = t % DEPTH;
    const int lane = threadIdx.x & 31;
    const int h = threadIdx.x >> 5;

    const float* qrow = qkv + (size_t)t * C3 + h * HD;
    const float q0 = qrow[lane]      * 8.0f;
    const float q1 = qrow[lane + 32] * 8.0f;

    int   nbt[KNBR];
    float sc [KNBR];
    #pragma unroll
    for (int kk = 0; kk < KNBR; kk++) {
        const int nb = __ldg(&which[n * KNBR + kk]);
        nbt[kk] = nb * DEPTH + d;
        const float* krow = qkv + (size_t)nbt[kk] * C3 + 512 + h * HD;
        float s = q0 * krow[lane] + q1 * krow[lane + 32];
        #pragma unroll
        for (int o = 16; o > 0; o >>= 1) s += __shfl_xor_sync(0xffffffffu, s, o);
        sc[kk] = (__ldg(&mask[n * KNBR + kk]) > 0) ? s : -1e9f;
    }

    float mx = sc[0];
    #pragma unroll
    for (int kk = 1; kk < KNBR; kk++) mx = fmaxf(mx, sc[kk]);
    float sum = 0.f;
    #pragma unroll
    for (int kk = 0; kk < KNBR; kk++) { sc[kk] = __expf(sc[kk] - mx); sum += sc[kk]; }
    const float rinv = 1.0f / sum;

    float o0 = 0.f, o1 = 0.f;
    #pragma unroll
    for (int kk = 0; kk < KNBR; kk++) {
        const float p = sc[kk] * rinv;
        const float* vrow = qkv + (size_t)nbt[kk] * C3 + 1024 + h * HD;
        o0 = fmaf(p, vrow[lane],      o0);
        o1 = fmaf(p, vrow[lane + 32], o1);
    }
    float* yr = y + (size_t)t * CDIM + h * HD;
    yr[lane]      = o0;
    yr[lane + 32] = o1;
}

// ---------------- launch ------------------------------------------------------
extern "C" void kernel_launch(void* const* d_in, const int* in_sizes, int n_in,
                              void* d_out, int out_size)
{
    const float* x      = (const float*)d_in[0];
    const int*   which  = (const int*)  d_in[1];
    const int*   mask   = (const int*)  d_in[2];
    const float* ln1_w  = (const float*)d_in[3];
    const float* ln1_b  = (const float*)d_in[4];
    const float* qkv_w  = (const float*)d_in[5];
    const float* qkv_b  = (const float*)d_in[6];
    const float* proj_w = (const float*)d_in[7];
    const float* proj_b = (const float*)d_in[8];
    const float* ln2_w  = (const float*)d_in[9];
    const float* ln2_b  = (const float*)d_in[10];
    const float* fc1_w  = (const float*)d_in[11];
    const float* fc1_b  = (const float*)d_in[12];
    const float* fc2_w  = (const float*)d_in[13];
    const float* fc2_b  = (const float*)d_in[14];
    float* out = (float*)d_out;

    float *p_xn, *p_qkv, *p_y, *p_x1, *p_h;
    cudaGetSymbolAddress((void**)&p_xn,  g_xn);
    cudaGetSymbolAddress((void**)&p_qkv, g_qkv);
    cudaGetSymbolAddress((void**)&p_y,   g_y);
    cudaGetSymbolAddress((void**)&p_x1,  g_x1);
    cudaGetSymbolAddress((void**)&p_h,   g_h);

    const int mtiles = (NTOK + 127) / 128;   // 161

    // 1) LN1
    ln_kernel<<<NTOK, 128>>>(x, ln1_w, ln1_b, p_xn);
    // 2) qkv = xn @ qkv_w^T + qkv_b      [20496 x 1536], K=512
    tc_gemm<0, CDIM><<<dim3(C3 / 128, mtiles), 256>>>(p_xn, qkv_w, qkv_b, nullptr,
                                                      p_qkv, NTOK, C3);
    // 3) sparse attention -> y
    attn_kernel<<<NTOK, 256>>>(p_qkv, which, mask, p_y);
    // 4) x1 = x + y @ proj_w^T + proj_b  K=512
    tc_gemm<2, CDIM><<<dim3(CDIM / 128, mtiles), 256>>>(p_y, proj_w, proj_b, x,
                                                        p_x1, NTOK, CDIM);
    // 5) LN2
    ln_kernel<<<NTOK, 128>>>(p_x1, ln2_w, ln2_b, p_xn);
    // 6) h = gelu(xn2 @ fc1_w^T + fc1_b)  [20496 x 2048], K=512
    tc_gemm<1, CDIM><<<dim3(HID / 128, mtiles), 256>>>(p_xn, fc1_w, fc1_b, nullptr,
                                                       p_h, NTOK, HID);
    // 7) out = x1 + h @ fc2_w^T + fc2_b   K=2048
    tc_gemm<2, HID><<<dim3(CDIM / 128, mtiles), 256>>>(p_h, fc2_w, fc2_b, p_x1,
                                                       out, NTOK, CDIM);
}